// round 5
// baseline (speedup 1.0000x reference)
#include <cuda_runtime.h>
#include <math.h>

typedef unsigned long long ull;

__device__ __forceinline__ void upk2(ull v, float& lo, float& hi) {
    asm("mov.b64 {%0, %1}, %2;" : "=f"(lo), "=f"(hi) : "l"(v));
}
__device__ __forceinline__ void fma2(ull& d, ull a, ull b) {
    asm("fma.rn.f32x2 %0, %1, %2, %0;" : "+l"(d) : "l"(a), "l"(b));
}

// ---------------------------------------------------------------------------
// Intermediate activation buffers (device globals — no allocation allowed).
// ---------------------------------------------------------------------------
__device__ float g_a1[38880000];   // 256*3*15^4
__device__ float g_a2[15925248];   // 256*3*12^4
__device__ float g_a3[6718464];    // 256*4*9^4
__device__ float g_a4[1658880];    // 256*5*6^4

__host__ __device__ constexpr int pad4(int x) { return (x + 3) & ~3; }

// ---------------------------------------------------------------------------
// Row engine v6. SMEM holds two copies of the tile with row pitch P (mult 4):
//   c0[rb+k] = x[k], c1[rb+k] = x[k+1]  (shift within each row)
// Even output-pairs  (x[2j],x[2j+1])  = LDS.128 from c0 (2 pairs per load).
// Odd  output-pairs  (x[2j+1],x[2j+2])= LDS.128 from c1.
// Registers ARE the packed pairs — zero packing instructions.
// Weights pre-duplicated float2, kw-permuted [w0,w2,w1,w3] per co (stride 4).
// ---------------------------------------------------------------------------
template<int CO, int K, int RP>
__device__ __forceinline__ void row_v6(const float* __restrict__ c0,
                                       const float* __restrict__ c1,
                                       int rb,
                                       const float2* __restrict__ wq,
                                       ull (&acc)[CO][RP])
{
    constexpr int NET = (K + 1) / 2;       // even taps (kw = 0,2)
    constexpr int NOT_ = K / 2;            // odd taps  (kw = 1,3)
    constexpr int NE = RP + NET - 1;
    constexpr int NO = RP + NOT_ - 1;
    constexpr int LE = (NE + 1) / 2;
    constexpr int LO = (NO + 1) / 2;

    {   // even taps
        ull E[2 * LE];
#pragma unroll
        for (int m = 0; m < LE; m++) {
            const ulonglong2 v = *reinterpret_cast<const ulonglong2*>(c0 + rb + 4 * m);
            E[2 * m] = v.x; E[2 * m + 1] = v.y;
        }
#pragma unroll
        for (int co = 0; co < CO; co++) {
            const ulonglong2 we = *reinterpret_cast<const ulonglong2*>(wq + co * 4);
#pragma unroll
            for (int j = 0; j < RP; j++) fma2(acc[co][j], E[j], we.x);
            if (NET > 1) {
#pragma unroll
                for (int j = 0; j < RP; j++) fma2(acc[co][j], E[1 + j], we.y);
            }
        }
    }
    {   // odd taps
        ull O[2 * LO];
#pragma unroll
        for (int m = 0; m < LO; m++) {
            const ulonglong2 v = *reinterpret_cast<const ulonglong2*>(c1 + rb + 4 * m);
            O[2 * m] = v.x; O[2 * m + 1] = v.y;
        }
        if (NOT_ == 2) {
#pragma unroll
            for (int co = 0; co < CO; co++) {
                const ulonglong2 wo = *reinterpret_cast<const ulonglong2*>(wq + co * 4 + 2);
#pragma unroll
                for (int j = 0; j < RP; j++) fma2(acc[co][j], O[j], wo.x);
#pragma unroll
                for (int j = 0; j < RP; j++) fma2(acc[co][j], O[1 + j], wo.y);
            }
        } else {
#pragma unroll
            for (int co = 0; co < CO; co++) {
                const ull wo = *reinterpret_cast<const ull*>(wq + co * 4 + 2);
#pragma unroll
                for (int j = 0; j < RP; j++) fma2(acc[co][j], O[j], wo);
            }
        }
    }
}

// Weight re-org: src layout [co][ci][kt][kd][kh][kw] ->
// s_w2[(blk*CO + co)*4 + pos(kw)] duplicated, blk = ((ci*K+kt)*K+kd)*K+kh,
// pos: even kw -> kw/2, odd kw -> 2 + kw/2.
template<int CIN, int CO, int K, int NTHR>
__device__ __forceinline__ void stage_weights(const float* __restrict__ w,
                                              float2* __restrict__ s_w2, int tid)
{
    constexpr int K4 = K * K * K * K;
    constexpr int NW = CO * CIN * K4;
    for (int i = tid; i < NW; i += NTHR) {
        int kw = i % K;        int r1 = i / K;
        int kh = r1 % K;       int r2 = r1 / K;
        int kd = r2 % K;       int r3 = r2 / K;
        int kt = r3 % K;       int r4 = r3 / K;
        int ci = r4 % CIN;     int co = r4 / CIN;
        int pos = (kw & 1) ? (2 + (kw >> 1)) : (kw >> 1);
        int blk = ((ci * K + kt) * K + kd) * K + kh;
        const float v = w[i];
        s_w2[(blk * CO + co) * 4 + pos] = make_float2(v, v);
    }
}

// ---------------------------------------------------------------------------
// convA: rolling t-slice conv (+bias+ReLU). Block = (b, t-chunk).
// Thread = (t_local, d, h) computes the full W row for all COUT.
// ---------------------------------------------------------------------------
template<int CIN, int COUT, int K, int S, int TLOC, int NTHR, int MINB>
__global__ void __launch_bounds__(NTHR, MINB)
convA(const float* __restrict__ in, float* __restrict__ out,
      const float* __restrict__ w, const float* __restrict__ bias)
{
    constexpr int O = S - K + 1, TCH = O / TLOC, NST = TLOC + K - 1;
    constexpr int S2 = S * S, S3 = S2 * S, S4 = S3 * S;
    constexpr int O2 = O * O, O3 = O2 * O;
    constexpr int P = pad4(S);
    constexpr int CAP = S2 * P;          // floats per slice copy
    constexpr int NACT = TLOC * O2;
    constexpr int RP = (O + 1) / 2;

    extern __shared__ __align__(16) float dsm[];   // c0[CAP] + c1[CAP]
    float* c0 = dsm;
    float* c1 = dsm + CAP;
    __shared__ __align__(16) float2 s_w2[CIN * K * K * K * COUT * 4];

    const int bt = blockIdx.x, tch = bt % TCH, b = bt / TCH;
    const int t0 = tch * TLOC, tid = threadIdx.x;

    stage_weights<CIN, COUT, K, NTHR>(w, s_w2, tid);

    const int tl = tid / O2, rem = tid - tl * O2, dd = rem / O, hh = rem - dd * O;
    const bool act = tid < NACT;
    const int row0 = (dd * S + hh);

    ull acc[COUT][RP];
#pragma unroll
    for (int c = 0; c < COUT; c++)
#pragma unroll
        for (int j = 0; j < RP; j++) acc[c][j] = 0ull;

    constexpr int NSL = CIN * NST;
#pragma unroll 1
    for (int idx = 0; idx < NSL; idx++) {
        const int ci = idx / NST, s = idx - ci * NST;
        __syncthreads();
        {
            const float* src = in + ((size_t)b * CIN + ci) * S4 + (size_t)(t0 + s) * S3;
            for (int i = tid; i < S3; i += NTHR) {
                const int r = i / S, k = i - r * S;
                const float v = src[i];
                const int base = r * P;
                c0[base + k] = v;
                if (k) c1[base + k - 1] = v;
            }
        }
        __syncthreads();

        const int kt = s - tl;
        if (act && kt >= 0 && kt < K) {
#pragma unroll 1
            for (int kd = 0; kd < K; kd++) {
#pragma unroll
                for (int kh = 0; kh < K; kh++) {
                    const int rb = (row0 + kd * S + kh) * P;
                    const int blk = ((ci * K + kt) * K + kd) * K + kh;
                    row_v6<COUT, K, RP>(c0, c1, rb, s_w2 + blk * COUT * 4, acc);
                }
            }
        }
    }

    if (act) {
        const int t = t0 + tl;
#pragma unroll
        for (int co = 0; co < COUT; co++) {
            const float bv = bias[co];
            float* op = out + ((size_t)b * COUT + co) * ((size_t)O * O3)
                            + (size_t)t * O3 + (dd * O + hh) * O;
#pragma unroll
            for (int j = 0; j < RP; j++) {
                float v0, v1; upk2(acc[co][j], v0, v1);
                op[2 * j] = fmaxf(v0 + bv, 0.0f);
                if (2 * j + 1 < O) op[2 * j + 1] = fmaxf(v1 + bv, 0.0f);
            }
        }
    }
}

// ---------------------------------------------------------------------------
// convB: whole-volume conv (L5) + fused FC1/ReLU/FC2/sigmoid head.
// Block = b; thread = (t,d,h). One input-channel 4D volume staged at a time.
// ---------------------------------------------------------------------------
template<int CIN, int COUT, int K, int S, int NTHR>
__global__ void __launch_bounds__(NTHR, 2)
convB_fc(const float* __restrict__ in, float* __restrict__ out,
         const float* __restrict__ w, const float* __restrict__ bias,
         const float* __restrict__ fc1w, const float* __restrict__ fc1b,
         const float* __restrict__ fc2w, const float* __restrict__ fc2b)
{
    constexpr int O = S - K + 1;
    constexpr int S2 = S * S, S3 = S2 * S, S4 = S3 * S;
    constexpr int O2 = O * O, O3 = O2 * O, O4 = O * O3;
    constexpr int P = pad4(S);
    constexpr int CAP = S3 * P;          // rows = (t,d,h)
    constexpr int NACT = O * O2;
    constexpr int RP = (O + 1) / 2;
    constexpr int NF = COUT * O4;        // 1280

    extern __shared__ __align__(16) float dsm[];   // c0[CAP] + c1[CAP]
    float* c0 = dsm;
    float* c1 = dsm + CAP;
    __shared__ __align__(16) float2 s_w2[CIN * K * K * K * COUT * 4];
    __shared__ float s_h[NF];
    __shared__ float s_so[33];

    const int b = blockIdx.x, tid = threadIdx.x;
    stage_weights<CIN, COUT, K, NTHR>(w, s_w2, tid);

    const int tl = tid / O2, rem = tid - tl * O2, dd = rem / O, hh = rem - dd * O;
    const bool act = tid < NACT;

    ull acc[COUT][RP];
#pragma unroll
    for (int c = 0; c < COUT; c++)
#pragma unroll
        for (int j = 0; j < RP; j++) acc[c][j] = 0ull;

#pragma unroll 1
    for (int ci = 0; ci < CIN; ci++) {
        __syncthreads();
        {
            const float* src = in + ((size_t)b * CIN + ci) * S4;
            for (int i = tid; i < S4; i += NTHR) {
                const int r = i / S, k = i - r * S;
                const float v = src[i];
                const int base = r * P;
                c0[base + k] = v;
                if (k) c1[base + k - 1] = v;
            }
        }
        __syncthreads();
        if (act) {
#pragma unroll 1
            for (int kt = 0; kt < K; kt++) {
#pragma unroll 1
                for (int kd = 0; kd < K; kd++) {
#pragma unroll
                    for (int kh = 0; kh < K; kh++) {
                        const int rb = (((tl + kt) * S + (dd + kd)) * S + (hh + kh)) * P;
                        const int blk = ((ci * K + kt) * K + kd) * K + kh;
                        row_v6<COUT, K, RP>(c0, c1, rb, s_w2 + blk * COUT * 4, acc);
                    }
                }
            }
        }
    }

    // conv output -> SMEM flat [co][t][d][h][w] with bias+ReLU
    if (act) {
#pragma unroll
        for (int co = 0; co < COUT; co++) {
            const float bv = bias[co];
            float* op = s_h + co * O4 + tl * O3 + (dd * O + hh) * O;
#pragma unroll
            for (int j = 0; j < RP; j++) {
                float v0, v1; upk2(acc[co][j], v0, v1);
                op[2 * j] = fmaxf(v0 + bv, 0.0f);
                if (2 * j + 1 < O) op[2 * j + 1] = fmaxf(v1 + bv, 0.0f);
            }
        }
    }
    __syncthreads();

    if (tid < 33) {
        const float* wr = fc1w + tid * NF;
        float a0 = 0.f, a1 = 0.f, a2 = 0.f, a3 = 0.f;
#pragma unroll 4
        for (int k = 0; k < NF; k += 4) {
            a0 = fmaf(s_h[k + 0], __ldg(wr + k + 0), a0);
            a1 = fmaf(s_h[k + 1], __ldg(wr + k + 1), a1);
            a2 = fmaf(s_h[k + 2], __ldg(wr + k + 2), a2);
            a3 = fmaf(s_h[k + 3], __ldg(wr + k + 3), a3);
        }
        s_so[tid] = fmaxf((a0 + a1) + (a2 + a3) + fc1b[tid], 0.0f);
    }
    __syncthreads();
    if (tid == 0) {
        float z = fc2b[0];
#pragma unroll
        for (int j = 0; j < 33; j++) z = fmaf(s_so[j], __ldg(fc2w + j), z);
        out[b] = 1.0f / (1.0f + expf(-z));
    }
}

// ---------------------------------------------------------------------------
// Inputs (metadata order):
// 0:x 1:w1 2:b1 3:w2 4:b2 5:w3 6:b3 7:w4 8:b4 9:w5 10:b5
// 11:fc1_w 12:fc1_b 13:fc2_w 14:fc2_b    -> out: [B,1] float32
// ---------------------------------------------------------------------------
extern "C" void kernel_launch(void* const* d_in, const int* in_sizes, int n_in,
                              void* d_out, int out_size)
{
    const float* x   = (const float*)d_in[0];
    const float* w1  = (const float*)d_in[1];
    const float* b1  = (const float*)d_in[2];
    const float* w2  = (const float*)d_in[3];
    const float* b2  = (const float*)d_in[4];
    const float* w3  = (const float*)d_in[5];
    const float* b3  = (const float*)d_in[6];
    const float* w4  = (const float*)d_in[7];
    const float* b4  = (const float*)d_in[8];
    const float* w5  = (const float*)d_in[9];
    const float* b5  = (const float*)d_in[10];
    const float* f1w = (const float*)d_in[11];
    const float* f1b = (const float*)d_in[12];
    const float* f2w = (const float*)d_in[13];
    const float* f2b = (const float*)d_in[14];

    const int B = in_sizes[0] / (18 * 18 * 18 * 18);

    float *a1, *a2, *a3, *a4;
    cudaGetSymbolAddress((void**)&a1, g_a1);
    cudaGetSymbolAddress((void**)&a2, g_a2);
    cudaGetSymbolAddress((void**)&a3, g_a3);
    cudaGetSymbolAddress((void**)&a4, g_a4);

    // dynamic SMEM = 2 copies * S2 (or S3) rows * pitch * 4B
    constexpr int SM1 = 2 * (18 * 18) * 20 * 4;           // 51840 B
    constexpr int SM2 = 2 * (15 * 15) * 16 * 4;           // 28800 B
    constexpr int SM3 = 2 * (12 * 12) * 12 * 4;           // 13824 B
    constexpr int SM4 = 2 * (9 * 9) * 12 * 4;             //  7776 B
    constexpr int SM5 = 2 * (6 * 6 * 6) * 8 * 4;          // 13824 B

    cudaFuncSetAttribute(convA<1, 3, 4, 18, 1, 256, 2>,
                         cudaFuncAttributeMaxDynamicSharedMemorySize, SM1);
    cudaFuncSetAttribute(convA<3, 3, 4, 15, 2, 288, 2>,
                         cudaFuncAttributeMaxDynamicSharedMemorySize, SM2);
    cudaFuncSetAttribute(convA<3, 4, 4, 12, 3, 256, 2>,
                         cudaFuncAttributeMaxDynamicSharedMemorySize, SM3);
    cudaFuncSetAttribute(convA<4, 5, 4, 9, 3, 128, 4>,
                         cudaFuncAttributeMaxDynamicSharedMemorySize, SM4);
    cudaFuncSetAttribute(convB_fc<5, 5, 3, 6, 128>,
                         cudaFuncAttributeMaxDynamicSharedMemorySize, SM5);

    // L1: 18^4 -> 15^4, 1->3, k=4   (grid 3840, 225/256 active)
    convA<1, 3, 4, 18, 1, 256, 2><<<B * 15, 256, SM1>>>(x,  a1, w1, b1);
    // L2: 15^4 -> 12^4, 3->3, k=4   (TLOC=2, grid 1536, 288/288 active)
    convA<3, 3, 4, 15, 2, 288, 2><<<B * 6, 288, SM2>>>(a1, a2, w2, b2);
    // L3: 12^4 -> 9^4, 3->4, k=4    (TLOC=3, grid 768, 243/256 active)
    convA<3, 4, 4, 12, 3, 256, 2><<<B * 3, 256, SM3>>>(a2, a3, w3, b3);
    // L4: 9^4 -> 6^4, 4->5, k=4     (TLOC=3, grid 512, 108/128 active)
    convA<4, 5, 4, 9, 3, 128, 4><<<B * 2, 128, SM4>>>(a3, a4, w4, b4);
    // L5: 6^4 -> 4^4, 5->5, k=3 + fused FC1/ReLU/FC2/sigmoid -> d_out [B,1]
    convB_fc<5, 5, 3, 6, 128><<<B, 128, SM5>>>(a4, (float*)d_out, w5, b5,
                                               f1w, f1b, f2w, f2b);
}

// round 6
// speedup vs baseline: 1.3601x; 1.3601x over previous
#include <cuda_runtime.h>
#include <math.h>

typedef unsigned long long ull;

__device__ __forceinline__ ull pk2(float lo, float hi) {
    ull r; asm("mov.b64 %0, {%1, %2};" : "=l"(r) : "f"(lo), "f"(hi)); return r;
}
__device__ __forceinline__ void upk2(ull v, float& lo, float& hi) {
    asm("mov.b64 {%0, %1}, %2;" : "=f"(lo), "=f"(hi) : "l"(v));
}
__device__ __forceinline__ void fma2(ull& d, ull a, ull b) {
    asm("fma.rn.f32x2 %0, %1, %2, %0;" : "+l"(d) : "l"(a), "l"(b));
}
__device__ __forceinline__ ull lds64w(const float2* p) {
    return *reinterpret_cast<const ull*>(p);
}

// ---------------------------------------------------------------------------
// Intermediate activation buffers (device globals — no allocation allowed).
// ---------------------------------------------------------------------------
__device__ float g_a1[38880000];   // 256*3*15^4
__device__ float g_a2[15925248];   // 256*3*12^4
__device__ float g_a3[6718464];    // 256*4*9^4
__device__ float g_a4[1658880];    // 256*5*6^4

__host__ __device__ constexpr int slice_pitch(int s3) { return (s3 + 6) & ~1; }

// ===========================================================================
// convHR: half-row FFMA2 conv for K=4 layers (+bias+ReLU).
// Block = (b, t). Thread = (d, h, half); each half-thread owns HP output
// pairs of the W row for all COUT. TLOC = 1 (one output t per block).
// acc regs = CO*HP (small!) -> high occupancy with FFMA2 throughput.
// ===========================================================================
template<int CIN, int CO, int K, int S, int NTHR, int MINB>
__global__ void __launch_bounds__(NTHR, MINB)
convHR(const float* __restrict__ in, float* __restrict__ out,
       const float* __restrict__ w, const float* __restrict__ bias)
{
    static_assert(K == 4, "convHR is specialized for K=4");
    constexpr int O  = S - K + 1;
    constexpr int HP = (O + 3) / 4;            // output pairs per half-thread
    constexpr int P  = (S & 1) ? S : (S + 1);  // odd pitch (bank spread + pad)
    constexpr int S2 = S * S, S3 = S2 * S, S4 = S3 * S;
    constexpr int K4 = K * K * K * K;
    constexpr int NW = CO * CIN * K4;
    constexpr int NWIN = 2 * HP + 3;           // floats per thread window

    extern __shared__ __align__(16) float dsm[];   // S2*P + 4
    __shared__ __align__(8) float2 s_w2[NW];

    const int bt = blockIdx.x;
    const int t  = bt % O;
    const int b  = bt / O;
    const int tid = threadIdx.x;

    for (int i = tid; i < NW; i += NTHR) {
        const float v = w[i];
        s_w2[i] = make_float2(v, v);
    }

    const int idx2 = tid >> 1;
    const int half = tid & 1;
    const int dd = idx2 / O, hh = idx2 - dd * O;
    const bool act = idx2 < O * O;
    const int w0 = half * (2 * HP);

    ull acc[CO][HP];
#pragma unroll
    for (int c = 0; c < CO; c++)
#pragma unroll
        for (int j = 0; j < HP; j++) acc[c][j] = 0ull;

#pragma unroll 1
    for (int idx = 0; idx < CIN * K; idx++) {
        const int ci = idx / K, s = idx - ci * K;   // kt = s (TLOC=1)
        __syncthreads();
        {
            const float* src = in + ((size_t)b * CIN + ci) * S4 + (size_t)(t + s) * S3;
            for (int i = tid; i < S3; i += NTHR) {
                const int r = i / S, k = i - r * S;
                dsm[r * P + k] = src[i];
            }
        }
        __syncthreads();

        if (act) {
#pragma unroll 1
            for (int kd = 0; kd < K; kd++) {
#pragma unroll
                for (int kh = 0; kh < K; kh++) {
                    const float* xp = dsm + ((dd + kd) * S + (hh + kh)) * P + w0;
                    float x[NWIN];
#pragma unroll
                    for (int m = 0; m < NWIN; m++) x[m] = xp[m];

                    ull E[HP + 1], Od[HP + 1];
#pragma unroll
                    for (int m = 0; m <= HP; m++) E[m]  = pk2(x[2 * m],     x[2 * m + 1]);
#pragma unroll
                    for (int m = 0; m <= HP; m++) Od[m] = pk2(x[2 * m + 1], x[2 * m + 2]);

                    const float2* wq = s_w2 + (((ci * K + s) * K + kd) * K + kh) * K;
#pragma unroll
                    for (int kw = 0; kw < K; kw++)
#pragma unroll
                        for (int co = 0; co < CO; co++) {
                            const ull wv = lds64w(wq + co * (CIN * K4) + kw);
#pragma unroll
                            for (int j = 0; j < HP; j++)
                                fma2(acc[co][j],
                                     (kw & 1) ? Od[(kw >> 1) + j] : E[(kw >> 1) + j],
                                     wv);
                        }
                }
            }
        }
    }

    if (act) {
#pragma unroll
        for (int co = 0; co < CO; co++) {
            const float bv = bias[co];
            float* op = out + ((((size_t)(b * CO + co) * O + t) * O + dd) * O + hh) * O;
#pragma unroll
            for (int j = 0; j < HP; j++) {
                float v0, v1; upk2(acc[co][j], v0, v1);
                const int wp = w0 + 2 * j;
                if (wp     < O) op[wp]     = fmaxf(v0 + bv, 0.0f);
                if (wp + 1 < O) op[wp + 1] = fmaxf(v1 + bv, 0.0f);
            }
        }
    }
}

// ===========================================================================
// convS: R1's proven scalar conv (+bias+ReLU). Block = (b, t-chunk).
// ===========================================================================
template<int CIN, int COUT, int K, int S, int TLOC, int NTHR>
__global__ void __launch_bounds__(NTHR)
convS(const float* __restrict__ in, float* __restrict__ out,
      const float* __restrict__ w, const float* __restrict__ bias)
{
    constexpr int O = S - K + 1, TCH = O / TLOC, NST = TLOC + K - 1;
    constexpr int S2 = S * S, S3 = S2 * S, S4 = S3 * S;
    constexpr int O2 = O * O, O3 = O2 * O;
    constexpr int KW4 = K * K * K * K;
    constexpr int NW = COUT * CIN * KW4;
    constexpr int NACT = TLOC * O2;

    __shared__ float s_slice[S3];
    __shared__ float s_w[NW];

    const int bt = blockIdx.x, tchunk = bt % TCH, b = bt / TCH;
    const int t0 = tchunk * TLOC, tid = threadIdx.x;

    for (int i = tid; i < NW; i += NTHR) s_w[i] = w[i];

    const int tl = tid / O2, rem = tid - tl * O2, dd = rem / O, hh = rem - dd * O;
    const bool act = tid < NACT;

    float acc[COUT][O];
#pragma unroll
    for (int c = 0; c < COUT; c++)
#pragma unroll
        for (int r = 0; r < O; r++) acc[c][r] = 0.0f;

#pragma unroll 1
    for (int ci = 0; ci < CIN; ci++) {
#pragma unroll 1
        for (int s = 0; s < NST; s++) {
            __syncthreads();
            const float* src = in + (size_t)(b * CIN + ci) * S4 + (size_t)(t0 + s) * S3;
            for (int i = tid; i < S3; i += NTHR) s_slice[i] = src[i];
            __syncthreads();

            const int kt = s - tl;
            if (act && kt >= 0 && kt < K) {
                const float* wb = s_w + (ci * K + kt) * (K * K * K);
#pragma unroll 1
                for (int kd = 0; kd < K; kd++) {
#pragma unroll
                    for (int kh = 0; kh < K; kh++) {
                        const float* rp = s_slice + (dd + kd) * S2 + (hh + kh) * S;
                        float row[S];
#pragma unroll
                        for (int x = 0; x < S; x++) row[x] = rp[x];

                        float wr[COUT][K];
#pragma unroll
                        for (int co = 0; co < COUT; co++)
#pragma unroll
                            for (int kw = 0; kw < K; kw++)
                                wr[co][kw] = wb[co * CIN * KW4 + (kd * K + kh) * K + kw];

#pragma unroll
                        for (int kw = 0; kw < K; kw++)
#pragma unroll
                            for (int r = 0; r < O; r++)
#pragma unroll
                                for (int co = 0; co < COUT; co++)
                                    acc[co][r] = fmaf(wr[co][kw], row[r + kw], acc[co][r]);
                    }
                }
            }
        }
    }

    if (act) {
        const int t = t0 + tl;
#pragma unroll
        for (int co = 0; co < COUT; co++) {
            const float bv = bias[co];
            float* op = out + (size_t)(b * COUT + co) * ((size_t)O * O3)
                            + (size_t)t * O3 + (dd * O + hh) * O;
#pragma unroll
            for (int r = 0; r < O; r++)
                op[r] = fmaxf(acc[co][r] + bv, 0.0f);
        }
    }
}

// ===========================================================================
// R2's 137us row engine + convB (verbatim behavior): whole-volume conv,
// double-buffered channel staging, optional fused FC head.
// ===========================================================================
template<int CO, int K, int RP, int COS>
__device__ __forceinline__ void row_r2(const float* __restrict__ rsrc,
                                       const float* __restrict__ wq,
                                       ull (&acc)[CO][RP])
{
    constexpr int RL = 2 * RP + K - 1;
    float row[RL];
#pragma unroll
    for (int x = 0; x < RL; x++) row[x] = rsrc[x];

    constexpr int NE = RP + 1;
    constexpr int NO = RP + (K >= 4 ? 1 : 0);
    ull rowE[NE], rowO[NO];
#pragma unroll
    for (int j = 0; j < NE; j++) rowE[j] = pk2(row[2 * j], row[2 * j + 1]);
#pragma unroll
    for (int j = 0; j < NO; j++) rowO[j] = pk2(row[2 * j + 1], row[2 * j + 2]);

#pragma unroll
    for (int kw = 0; kw < K; kw++) {
#pragma unroll
        for (int co = 0; co < CO; co++) {
            const float wv = wq[co * COS + kw];
            const ull w2 = pk2(wv, wv);
#pragma unroll
            for (int j = 0; j < RP; j++) {
                const ull a = (kw & 1) ? rowO[(kw >> 1) + j] : rowE[(kw >> 1) + j];
                fma2(acc[co][j], a, w2);
            }
        }
    }
}

template<int CIN, int COUT, int K, int S, int NTHR, bool FUSE_FC>
__global__ void __launch_bounds__(NTHR)
convB(const float* __restrict__ in, float* __restrict__ out,
      const float* __restrict__ w, const float* __restrict__ bias,
      const float* __restrict__ fc1w, const float* __restrict__ fc1b,
      const float* __restrict__ fc2w, const float* __restrict__ fc2b)
{
    constexpr int O = S - K + 1;
    constexpr int S2 = S * S, S3 = S2 * S, S4 = S3 * S;
    constexpr int O2 = O * O, O3 = O2 * O, O4 = O * O3;
    constexpr int K4 = K * K * K * K, NW = COUT * CIN * K4;
    constexpr int NACT = O * O2;
    constexpr int RP = (O + 1) / 2;
    constexpr int VP = slice_pitch(S4);
    constexpr int NF = COUT * O4;

    extern __shared__ float dsm[];           // 2 * VP
    __shared__ float s_w[NW];
    __shared__ float s_h[FUSE_FC ? NF : 1];
    __shared__ float s_so[FUSE_FC ? 33 : 1];

    const int b = blockIdx.x, tid = threadIdx.x;
    for (int i = tid; i < NW; i += NTHR) s_w[i] = w[i];

    const int tl = tid / O2, rem = tid - tl * O2, dd = rem / O, hh = rem - dd * O;
    const bool act = tid < NACT;

    ull acc[COUT][RP];
#pragma unroll
    for (int c = 0; c < COUT; c++)
#pragma unroll
        for (int j = 0; j < RP; j++) acc[c][j] = 0ull;

    {
        const float* src = in + (size_t)b * CIN * S4;
        for (int i = tid; i < S4; i += NTHR) dsm[i] = src[i];
    }
#pragma unroll 1
    for (int ci = 0; ci < CIN; ci++) {
        __syncthreads();
        if (ci + 1 < CIN) {
            const float* src = in + ((size_t)b * CIN + ci + 1) * S4;
            float* dst = dsm + ((ci + 1) & 1) * VP;
            for (int i = tid; i < S4; i += NTHR) dst[i] = src[i];
        }
        if (act) {
            const float* buf = dsm + (ci & 1) * VP;
#pragma unroll 1
            for (int kt = 0; kt < K; kt++) {
#pragma unroll 1
                for (int kd = 0; kd < K; kd++) {
#pragma unroll
                    for (int kh = 0; kh < K; kh++) {
                        const float* rp_ = buf + (tl + kt) * S3 + (dd + kd) * S2 + (hh + kh) * S;
                        const float* wq  = s_w + (((ci * K + kt) * K + kd) * K + kh) * K;
                        row_r2<COUT, K, RP, CIN * K4>(rp_, wq, acc);
                    }
                }
            }
        }
    }

    if (!FUSE_FC) {
        if (act) {
#pragma unroll
            for (int co = 0; co < COUT; co++) {
                const float bv = bias[co];
                float* op = out + ((size_t)b * COUT + co) * (size_t)O4
                                + (size_t)tl * O3 + (dd * O + hh) * O;
#pragma unroll
                for (int j = 0; j < RP; j++) {
                    float v0, v1; upk2(acc[co][j], v0, v1);
                    op[2 * j] = fmaxf(v0 + bv, 0.0f);
                    if (2 * j + 1 < O) op[2 * j + 1] = fmaxf(v1 + bv, 0.0f);
                }
            }
        }
    } else {
        if (act) {
#pragma unroll
            for (int co = 0; co < COUT; co++) {
                const float bv = bias[co];
                float* op = s_h + co * O4 + tl * O3 + (dd * O + hh) * O;
#pragma unroll
                for (int j = 0; j < RP; j++) {
                    float v0, v1; upk2(acc[co][j], v0, v1);
                    op[2 * j] = fmaxf(v0 + bv, 0.0f);
                    if (2 * j + 1 < O) op[2 * j + 1] = fmaxf(v1 + bv, 0.0f);
                }
            }
        }
        __syncthreads();
        if (tid < 33) {
            const float* wr = fc1w + tid * NF;
            float a0 = 0.f, a1 = 0.f, a2 = 0.f, a3 = 0.f;
#pragma unroll 4
            for (int k = 0; k < NF; k += 4) {
                a0 = fmaf(s_h[k + 0], __ldg(wr + k + 0), a0);
                a1 = fmaf(s_h[k + 1], __ldg(wr + k + 1), a1);
                a2 = fmaf(s_h[k + 2], __ldg(wr + k + 2), a2);
                a3 = fmaf(s_h[k + 3], __ldg(wr + k + 3), a3);
            }
            s_so[tid] = fmaxf((a0 + a1) + (a2 + a3) + fc1b[tid], 0.0f);
        }
        __syncthreads();
        if (tid == 0) {
            float z = fc2b[0];
#pragma unroll
            for (int j = 0; j < 33; j++) z = fmaf(s_so[j], __ldg(fc2w + j), z);
            out[b] = 1.0f / (1.0f + expf(-z));
        }
    }
}

// ---------------------------------------------------------------------------
// Inputs (metadata order):
// 0:x 1:w1 2:b1 3:w2 4:b2 5:w3 6:b3 7:w4 8:b4 9:w5 10:b5
// 11:fc1_w 12:fc1_b 13:fc2_w 14:fc2_b    -> out: [B,1] float32
// ---------------------------------------------------------------------------
extern "C" void kernel_launch(void* const* d_in, const int* in_sizes, int n_in,
                              void* d_out, int out_size)
{
    const float* x   = (const float*)d_in[0];
    const float* w1  = (const float*)d_in[1];
    const float* b1  = (const float*)d_in[2];
    const float* w2  = (const float*)d_in[3];
    const float* b2  = (const float*)d_in[4];
    const float* w3  = (const float*)d_in[5];
    const float* b3  = (const float*)d_in[6];
    const float* w4  = (const float*)d_in[7];
    const float* b4  = (const float*)d_in[8];
    const float* w5  = (const float*)d_in[9];
    const float* b5  = (const float*)d_in[10];
    const float* f1w = (const float*)d_in[11];
    const float* f1b = (const float*)d_in[12];
    const float* f2w = (const float*)d_in[13];
    const float* f2b = (const float*)d_in[14];

    const int B = in_sizes[0] / (18 * 18 * 18 * 18);

    float *a1, *a2, *a3, *a4;
    cudaGetSymbolAddress((void**)&a1, g_a1);
    cudaGetSymbolAddress((void**)&a2, g_a2);
    cudaGetSymbolAddress((void**)&a3, g_a3);
    cudaGetSymbolAddress((void**)&a4, g_a4);

    // HR dynamic SMEM: S2 * P + 4 floats
    constexpr int SM1 = (18 * 18 * 19 + 4) * 4;                  // 24640 B
    constexpr int SM2 = (15 * 15 * 15 + 4) * 4;                  // 13516 B
    constexpr int SM4 = 2 * slice_pitch(9 * 9 * 9 * 9) * 4;      // 52528 B
    constexpr int SM5 = 2 * slice_pitch(6 * 6 * 6 * 6) * 4;      // 10416 B

    cudaFuncSetAttribute(convHR<1, 3, 4, 18, 480, 2>,
                         cudaFuncAttributeMaxDynamicSharedMemorySize, SM1);
    cudaFuncSetAttribute(convHR<3, 3, 4, 15, 288, 3>,
                         cudaFuncAttributeMaxDynamicSharedMemorySize, SM2);
    cudaFuncSetAttribute(convB<4, 5, 4, 9, 224, false>,
                         cudaFuncAttributeMaxDynamicSharedMemorySize, SM4);
    cudaFuncSetAttribute(convB<5, 5, 3, 6, 128, true>,
                         cudaFuncAttributeMaxDynamicSharedMemorySize, SM5);

    // L1: 18^4 -> 15^4, 1->3, k=4   (HR: grid 3840, 450/480 active)
    convHR<1, 3, 4, 18, 480, 2><<<B * 15, 480, SM1>>>(x,  a1, w1, b1);
    // L2: 15^4 -> 12^4, 3->3, k=4   (HR: grid 3072, 288/288 active)
    convHR<3, 3, 4, 15, 288, 3><<<B * 12, 288, SM2>>>(a1, a2, w2, b2);
    // L3: 12^4 -> 9^4, 3->4, k=4    (scalar R1: grid 768, 243/256 active)
    convS<3, 4, 4, 12, 3, 256><<<B * 3, 256>>>(a2, a3, w3, b3);
    // L4: 9^4 -> 6^4, 4->5, k=4     (R2 convB: grid 256, 216/224 active)
    convB<4, 5, 4, 9, 224, false><<<B, 224, SM4>>>(a3, a4, w4, b4,
                                                   nullptr, nullptr, nullptr, nullptr);
    // L5: 6^4 -> 4^4, 5->5, k=3 + fused FC1/ReLU/FC2/sigmoid -> d_out [B,1]
    convB<5, 5, 3, 6, 128, true><<<B, 128, SM5>>>(a4, (float*)d_out, w5, b5,
                                                  f1w, f1b, f2w, f2b);
}

// round 7
// speedup vs baseline: 1.5031x; 1.1052x over previous
#include <cuda_runtime.h>
#include <math.h>

typedef unsigned long long ull;

// ---------------------------------------------------------------------------
// Packed f32x2 helpers (used by convB only — measured fastest for L4)
// ---------------------------------------------------------------------------
__device__ __forceinline__ ull pk2(float lo, float hi) {
    ull r; asm("mov.b64 %0, {%1, %2};" : "=l"(r) : "f"(lo), "f"(hi)); return r;
}
__device__ __forceinline__ void upk2(ull v, float& lo, float& hi) {
    asm("mov.b64 {%0, %1}, %2;" : "=f"(lo), "=f"(hi) : "l"(v));
}
__device__ __forceinline__ void fma2(ull& d, ull a, ull b) {
    asm("fma.rn.f32x2 %0, %1, %2, %0;" : "+l"(d) : "l"(a), "l"(b));
}

// ---------------------------------------------------------------------------
// Intermediate activation buffers (device globals — no allocation allowed).
// Layouts all [B, C, T, D, H, W] contiguous.
// ---------------------------------------------------------------------------
__device__ float g_a1[38880000];   // 256*3*15^4
__device__ float g_a2[15925248];   // 256*3*12^4
__device__ float g_a3[6718464];    // 256*4*9^4
__device__ float g_a4[1658880];    // 256*5*6^4
__device__ float g_a5[327680];     // 256*5*4^4  (== flattened [256,1280])

__host__ __device__ constexpr int slice_pitch(int s3) { return (s3 + 6) & ~1; }

// ===========================================================================
// convS: R1's proven scalar conv (+bias+ReLU). Block = (b, t-chunk).
// Thread = (t_local, d, h) computes the full W row for all COUT.
// MINB picks the reg cap: 65536/(NTHR*MINB).
// ===========================================================================
template<int CIN, int COUT, int K, int S, int TLOC, int NTHR, int MINB>
__global__ void __launch_bounds__(NTHR, MINB)
convS(const float* __restrict__ in, float* __restrict__ out,
      const float* __restrict__ w, const float* __restrict__ bias)
{
    constexpr int O = S - K + 1, TCH = O / TLOC, NST = TLOC + K - 1;
    constexpr int S2 = S * S, S3 = S2 * S, S4 = S3 * S;
    constexpr int O2 = O * O, O3 = O2 * O;
    constexpr int KW4 = K * K * K * K;
    constexpr int NW = COUT * CIN * KW4;
    constexpr int NACT = TLOC * O2;

    __shared__ float s_slice[S3];
    __shared__ float s_w[NW];

    const int bt = blockIdx.x, tchunk = bt % TCH, b = bt / TCH;
    const int t0 = tchunk * TLOC, tid = threadIdx.x;

    for (int i = tid; i < NW; i += NTHR) s_w[i] = w[i];

    const int tl = tid / O2, rem = tid - tl * O2, dd = rem / O, hh = rem - dd * O;
    const bool act = tid < NACT;

    float acc[COUT][O];
#pragma unroll
    for (int c = 0; c < COUT; c++)
#pragma unroll
        for (int r = 0; r < O; r++) acc[c][r] = 0.0f;

#pragma unroll 1
    for (int ci = 0; ci < CIN; ci++) {
#pragma unroll 1
        for (int s = 0; s < NST; s++) {
            __syncthreads();
            const float* src = in + (size_t)(b * CIN + ci) * S4 + (size_t)(t0 + s) * S3;
            for (int i = tid; i < S3; i += NTHR) s_slice[i] = src[i];
            __syncthreads();

            const int kt = s - tl;
            if (act && kt >= 0 && kt < K) {
                const float* wb = s_w + (ci * K + kt) * (K * K * K);
#pragma unroll 1
                for (int kd = 0; kd < K; kd++) {
#pragma unroll
                    for (int kh = 0; kh < K; kh++) {
                        const float* rp = s_slice + (dd + kd) * S2 + (hh + kh) * S;
                        float row[S];
#pragma unroll
                        for (int x = 0; x < S; x++) row[x] = rp[x];

                        float wr[COUT][K];
#pragma unroll
                        for (int co = 0; co < COUT; co++)
#pragma unroll
                            for (int kw = 0; kw < K; kw++)
                                wr[co][kw] = wb[co * CIN * KW4 + (kd * K + kh) * K + kw];

#pragma unroll
                        for (int kw = 0; kw < K; kw++)
#pragma unroll
                            for (int r = 0; r < O; r++)
#pragma unroll
                                for (int co = 0; co < COUT; co++)
                                    acc[co][r] = fmaf(wr[co][kw], row[r + kw], acc[co][r]);
                    }
                }
            }
        }
    }

    if (act) {
        const int t = t0 + tl;
#pragma unroll
        for (int co = 0; co < COUT; co++) {
            const float bv = bias[co];
            float* op = out + (size_t)(b * COUT + co) * ((size_t)O * O3)
                            + (size_t)t * O3 + (dd * O + hh) * O;
#pragma unroll
            for (int r = 0; r < O; r++)
                op[r] = fmaxf(acc[co][r] + bv, 0.0f);
        }
    }
}

// ===========================================================================
// convB (R6's measured-fastest L4): whole-volume FFMA2 conv, block = b,
// thread = (t,d,h), double-buffered channel staging.
// ===========================================================================
template<int CO, int K, int RP, int COS>
__device__ __forceinline__ void row_r2(const float* __restrict__ rsrc,
                                       const float* __restrict__ wq,
                                       ull (&acc)[CO][RP])
{
    constexpr int RL = 2 * RP + K - 1;
    float row[RL];
#pragma unroll
    for (int x = 0; x < RL; x++) row[x] = rsrc[x];

    constexpr int NE = RP + 1;
    constexpr int NO = RP + (K >= 4 ? 1 : 0);
    ull rowE[NE], rowO[NO];
#pragma unroll
    for (int j = 0; j < NE; j++) rowE[j] = pk2(row[2 * j], row[2 * j + 1]);
#pragma unroll
    for (int j = 0; j < NO; j++) rowO[j] = pk2(row[2 * j + 1], row[2 * j + 2]);

#pragma unroll
    for (int kw = 0; kw < K; kw++) {
#pragma unroll
        for (int co = 0; co < CO; co++) {
            const float wv = wq[co * COS + kw];
            const ull w2 = pk2(wv, wv);
#pragma unroll
            for (int j = 0; j < RP; j++) {
                const ull a = (kw & 1) ? rowO[(kw >> 1) + j] : rowE[(kw >> 1) + j];
                fma2(acc[co][j], a, w2);
            }
        }
    }
}

template<int CIN, int COUT, int K, int S, int NTHR>
__global__ void __launch_bounds__(NTHR)
convB(const float* __restrict__ in, float* __restrict__ out,
      const float* __restrict__ w, const float* __restrict__ bias)
{
    constexpr int O = S - K + 1;
    constexpr int S2 = S * S, S3 = S2 * S, S4 = S3 * S;
    constexpr int O2 = O * O, O3 = O2 * O, O4 = O * O3;
    constexpr int K4 = K * K * K * K, NW = COUT * CIN * K4;
    constexpr int NACT = O * O2;
    constexpr int RP = (O + 1) / 2;
    constexpr int VP = slice_pitch(S4);

    extern __shared__ float dsm[];           // 2 * VP
    __shared__ float s_w[NW];

    const int b = blockIdx.x, tid = threadIdx.x;
    for (int i = tid; i < NW; i += NTHR) s_w[i] = w[i];

    const int tl = tid / O2, rem = tid - tl * O2, dd = rem / O, hh = rem - dd * O;
    const bool act = tid < NACT;

    ull acc[COUT][RP];
#pragma unroll
    for (int c = 0; c < COUT; c++)
#pragma unroll
        for (int j = 0; j < RP; j++) acc[c][j] = 0ull;

    {
        const float* src = in + (size_t)b * CIN * S4;
        for (int i = tid; i < S4; i += NTHR) dsm[i] = src[i];
    }
#pragma unroll 1
    for (int ci = 0; ci < CIN; ci++) {
        __syncthreads();
        if (ci + 1 < CIN) {
            const float* src = in + ((size_t)b * CIN + ci + 1) * S4;
            float* dst = dsm + ((ci + 1) & 1) * VP;
            for (int i = tid; i < S4; i += NTHR) dst[i] = src[i];
        }
        if (act) {
            const float* buf = dsm + (ci & 1) * VP;
#pragma unroll 1
            for (int kt = 0; kt < K; kt++) {
#pragma unroll 1
                for (int kd = 0; kd < K; kd++) {
#pragma unroll
                    for (int kh = 0; kh < K; kh++) {
                        const float* rp_ = buf + (tl + kt) * S3 + (dd + kd) * S2 + (hh + kh) * S;
                        const float* wq  = s_w + (((ci * K + kt) * K + kd) * K + kh) * K;
                        row_r2<COUT, K, RP, CIN * K4>(rp_, wq, acc);
                    }
                }
            }
        }
    }

    if (act) {
#pragma unroll
        for (int co = 0; co < COUT; co++) {
            const float bv = bias[co];
            float* op = out + ((size_t)b * COUT + co) * (size_t)O4
                            + (size_t)tl * O3 + (dd * O + hh) * O;
#pragma unroll
            for (int j = 0; j < RP; j++) {
                float v0, v1; upk2(acc[co][j], v0, v1);
                op[2 * j] = fmaxf(v0 + bv, 0.0f);
                if (2 * j + 1 < O) op[2 * j + 1] = fmaxf(v1 + bv, 0.0f);
            }
        }
    }
}

// ---------------------------------------------------------------------------
// Fused FC1(1280->33) + ReLU + FC2(33->1) + sigmoid. One block per batch row.
// (R1's proven head.)
// ---------------------------------------------------------------------------
__global__ void __launch_bounds__(64)
fc_head(const float* __restrict__ h,
        const float* __restrict__ fc1w, const float* __restrict__ fc1b,
        const float* __restrict__ fc2w, const float* __restrict__ fc2b,
        float* __restrict__ out)
{
    __shared__ float sh[1280];
    __shared__ float so[33];
    const int b = blockIdx.x;

    for (int i = threadIdx.x; i < 1280; i += 64) sh[i] = h[(size_t)b * 1280 + i];
    __syncthreads();

    const int co = threadIdx.x;
    if (co < 33) {
        float a = 0.0f;
        const float* wr = fc1w + co * 1280;
#pragma unroll 4
        for (int k = 0; k < 1280; k++) a = fmaf(sh[k], __ldg(&wr[k]), a);
        so[co] = fmaxf(a + fc1b[co], 0.0f);
    }
    __syncthreads();

    if (threadIdx.x == 0) {
        float z = fc2b[0];
#pragma unroll
        for (int j = 0; j < 33; j++) z = fmaf(so[j], __ldg(&fc2w[j]), z);
        out[b] = 1.0f / (1.0f + expf(-z));
    }
}

// ---------------------------------------------------------------------------
// Inputs (metadata order):
// 0:x 1:w1 2:b1 3:w2 4:b2 5:w3 6:b3 7:w4 8:b4 9:w5 10:b5
// 11:fc1_w 12:fc1_b 13:fc2_w 14:fc2_b    -> out: [B,1] float32
// ---------------------------------------------------------------------------
extern "C" void kernel_launch(void* const* d_in, const int* in_sizes, int n_in,
                              void* d_out, int out_size)
{
    const float* x   = (const float*)d_in[0];
    const float* w1  = (const float*)d_in[1];
    const float* b1  = (const float*)d_in[2];
    const float* w2  = (const float*)d_in[3];
    const float* b2  = (const float*)d_in[4];
    const float* w3  = (const float*)d_in[5];
    const float* b3  = (const float*)d_in[6];
    const float* w4  = (const float*)d_in[7];
    const float* b4  = (const float*)d_in[8];
    const float* w5  = (const float*)d_in[9];
    const float* b5  = (const float*)d_in[10];
    const float* f1w = (const float*)d_in[11];
    const float* f1b = (const float*)d_in[12];
    const float* f2w = (const float*)d_in[13];
    const float* f2b = (const float*)d_in[14];

    const int B = in_sizes[0] / (18 * 18 * 18 * 18);

    float *a1, *a2, *a3, *a4, *a5;
    cudaGetSymbolAddress((void**)&a1, g_a1);
    cudaGetSymbolAddress((void**)&a2, g_a2);
    cudaGetSymbolAddress((void**)&a3, g_a3);
    cudaGetSymbolAddress((void**)&a4, g_a4);
    cudaGetSymbolAddress((void**)&a5, g_a5);

    constexpr int SM4 = 2 * slice_pitch(9 * 9 * 9 * 9) * 4;      // 52528 B

    cudaFuncSetAttribute(convB<4, 5, 4, 9, 224>,
                         cudaFuncAttributeMaxDynamicSharedMemorySize, SM4);

    // L1: 18^4 -> 15^4, 1->3, k=4   (R1 exact: grid 3840, 225/256 active)
    convS<1, 3, 4, 18, 1, 256, 2><<<B * 15, 256>>>(x,  a1, w1, b1);
    // L2: 15^4 -> 12^4, 3->3, k=4   (NEW: 160 thr, 144 active = 90%,
    //     reg cap 81 -> 5 CTAs/SM -> ~22.5 active warps/SM vs R1's 13.5)
    convS<3, 3, 4, 15, 1, 160, 5><<<B * 12, 160>>>(a1, a2, w2, b2);
    // L3: 12^4 -> 9^4, 3->4, k=4    (R1 exact: grid 768, 243/256 active)
    convS<3, 4, 4, 12, 3, 256, 2><<<B * 3, 256>>>(a2, a3, w3, b3);
    // L4: 9^4 -> 6^4, 4->5, k=4     (R6 convB, measured 123us)
    convB<4, 5, 4, 9, 224><<<B, 224, SM4>>>(a3, a4, w4, b4);
    // L5: 6^4 -> 4^4, 5->5, k=3     (R1 exact)
    convS<5, 5, 3, 6, 4, 128, 2><<<B, 128>>>(a4, a5, w5, b5);
    // FC head: [B,1280] -> [B,33] -> [B,1] sigmoid (R1 exact)
    fc_head<<<B, 64>>>(a5, f1w, f1b, f2w, f2b, (float*)d_out);
}